// round 9
// baseline (speedup 1.0000x reference)
#include <cuda_runtime.h>
#include <cuda_fp16.h>

#define NN 100000
#define EE 1600000
#define DD 64
#define SCAN_BS 1024
#define SCAN_NB ((NN + SCAN_BS - 1) / SCAN_BS)   // 98

// ---- scratch (static device globals; no allocation anywhere) ----
__device__ float    g_zbuf[2 * NN];            // [dr | cnt], one memset
__device__ int      g_rp[NN + 1];              // CSR row_ptr (by dst)
__device__ int      g_cur[NN];                 // scatter cursors
__device__ int      g_bsum[SCAN_NB];           // scan block sums
__device__ float    g_dv[NN];                  // dinv (written by k_gemm0)
__device__ unsigned g_epk[EE];                 // CSR: (src<<15) | fp16(w) sans sign
__device__ __align__(16) __half g_hsh[NN * DD];   // fp16: dinv * (x@W1)
__device__ __align__(16) __half g_hsh2[NN * DD];  // fp16: dinv * (x2@W2)
__device__ float g_h3s[NN];

__device__ __forceinline__ float guard1(float v) { return v > 0.f ? v : 1.f; }

__device__ __forceinline__ unsigned f2tf32(float v) {
    unsigned t;
    asm("cvt.rna.tf32.f32 %0, %1;" : "=r"(t) : "f"(v));
    return t;
}

__device__ __forceinline__ void mma_tf32(float* d,
                                         unsigned a0, unsigned a1, unsigned a2, unsigned a3,
                                         unsigned b0, unsigned b1) {
    asm volatile(
        "mma.sync.aligned.m16n8k8.row.col.f32.tf32.tf32.f32 "
        "{%0,%1,%2,%3}, {%4,%5,%6,%7}, {%8,%9}, {%0,%1,%2,%3};"
        : "+f"(d[0]), "+f"(d[1]), "+f"(d[2]), "+f"(d[3])
        : "r"(a0), "r"(a1), "r"(a2), "r"(a3), "r"(b0), "r"(b1));
}

__device__ __forceinline__ void dec_epk(unsigned v, int& s, float& w) {
    s = (int)(v >> 15);
    w = __half2float(__ushort_as_half((unsigned short)(v & 0x7FFFu)));
}
__device__ __forceinline__ float dec_w(unsigned v) {
    return __half2float(__ushort_as_half((unsigned short)(v & 0x7FFFu)));
}

// ---------------- precompute ----------------

__global__ void k_pre1(const int* __restrict__ src, const int* __restrict__ dst,
                       const float* __restrict__ ev,
                       float* __restrict__ dr, int* __restrict__ cnt, int E) {
    int e = blockIdx.x * blockDim.x + threadIdx.x;
    if (e >= E) return;
    atomicAdd(&dr[src[e]], ev[e]);
    atomicAdd(&cnt[dst[e]], 1);
}

__global__ void k_scan1(const int* __restrict__ cnt, int* __restrict__ rp,
                        int* __restrict__ bsum, int N) {
    __shared__ int ws[32];
    int t = threadIdx.x;
    int lane = t & 31, wid = t >> 5;
    int i = blockIdx.x * SCAN_BS + t;
    int v = (i < N) ? cnt[i] : 0;
    int x = v;
#pragma unroll
    for (int o = 1; o < 32; o <<= 1) {
        int y = __shfl_up_sync(0xffffffffu, x, o);
        if (lane >= o) x += y;
    }
    if (lane == 31) ws[wid] = x;
    __syncthreads();
    if (wid == 0) {
        int s = ws[lane];
#pragma unroll
        for (int o = 1; o < 32; o <<= 1) {
            int y = __shfl_up_sync(0xffffffffu, s, o);
            if (lane >= o) s += y;
        }
        ws[lane] = s;
    }
    __syncthreads();
    int incl = x + (wid ? ws[wid - 1] : 0);
    if (i < N) rp[i] = incl - v;
    if (t == SCAN_BS - 1) bsum[blockIdx.x] = incl;
}

__global__ void k_scan3(int* __restrict__ rp, int* __restrict__ cur,
                        const int* __restrict__ bsum, int N, int E) {
    __shared__ int sh[128];
    int t = threadIdx.x;
    if (t < 128) sh[t] = (t < SCAN_NB) ? bsum[t] : 0;
    __syncthreads();
#pragma unroll
    for (int o = 1; o < 128; o <<= 1) {
        int add = (t >= o && t < 128) ? sh[t - o] : 0;
        __syncthreads();
        if (t < 128) sh[t] += add;
        __syncthreads();
    }
    int i = blockIdx.x * blockDim.x + t;
    if (i >= N) return;
    int blk = i >> 10;
    int off = blk ? sh[blk - 1] : 0;
    int r = rp[i] + off;
    rp[i] = r;
    cur[i] = r;
    if (i == 0) rp[N] = E;
}

// w_hat compute + packed CSR scatter (no deg atomics)
__global__ void k_scatter(const int* __restrict__ src, const int* __restrict__ dst,
                          const float* __restrict__ ev, const float* __restrict__ dr,
                          int* __restrict__ cur, unsigned* __restrict__ epk, int E) {
    int e = blockIdx.x * blockDim.x + threadIdx.x;
    if (e >= E) return;
    int s = src[e], d = dst[e];
    float w = ev[e] / (guard1(__ldg(&dr[s])) * guard1(__ldg(&dr[d])));
    int p = atomicAdd(&cur[d], 1);
    unsigned hb = (unsigned)__half_as_ushort(__float2half_rn(w));  // w>0: bit15=0
    epk[p] = ((unsigned)s << 15) | hb;
}

// ---------------- layers ----------------

#define XA 68   // xs stride: conflict-free A-frag loads
#define WB 72   // Ws stride: conflict-free B-frag loads

// Layer 1 GEMM. Also computes deg (sum of epk w per row) -> dv[] for all
// later kernels, and rowsum(feat). hsh = half(dv/rowsum * feat@W1).
__global__ void k_gemm0(const float* __restrict__ in, const float* __restrict__ W,
                        const int* __restrict__ rp, const unsigned* __restrict__ epk,
                        float* __restrict__ dvout, __half* __restrict__ hsh, int N) {
    __shared__ float Ws[DD * WB];
    __shared__ float xs[DD * XA];
    __shared__ float sdg[64];
    __shared__ float scal[64];
    int tid = threadIdx.x;
    int warp = tid >> 5, lane = tid & 31;
    int row0 = blockIdx.x * 64;

#pragma unroll
    for (int it = 0; it < 16; it++) {
        int i = it * 256 + tid;
        Ws[(i >> 6) * WB + (i & 63)] = __uint_as_float(f2tf32(W[i]));
    }
#pragma unroll
    for (int it = 0; it < 16; it++) {
        int i = it * 256 + tid;
        int r = i >> 6, c = i & 63;
        int row = row0 + r;
        xs[r * XA + c] = (row < N) ? in[(size_t)row * DD + c] : 0.f;
    }
    // deg sums: warp per 8 rows
#pragma unroll
    for (int q = 0; q < 8; q++) {
        int r = (warp << 3) + q;
        int n = row0 + r;
        float s = 0.f;
        if (n < N) {
            int beg = rp[n], end = rp[n + 1];
            for (int j = beg + lane; j < end; j += 32) s += dec_w(__ldg(&epk[j]));
        }
#pragma unroll
        for (int o = 16; o > 0; o >>= 1) s += __shfl_xor_sync(0xffffffffu, s, o);
        if (lane == 0) sdg[r] = s;
    }
    __syncthreads();
    if (tid < 64) {
        int row = row0 + tid;
        float s = 0.f;
        const float* xr = &xs[tid * XA];
#pragma unroll
        for (int c = 0; c < DD; c++) s += xr[c];
        float dv = rsqrtf(1.f + sdg[tid]);
        scal[tid] = dv / fmaxf(s, 1e-30f);
        if (row < N) dvout[row] = dv;
    }
    __syncthreads();
#pragma unroll
    for (int it = 0; it < 16; it++) {
        int i = it * 256 + tid;
        int r = i >> 6, c = i & 63;
        xs[r * XA + c] = __uint_as_float(f2tf32(xs[r * XA + c]));
    }
    __syncthreads();

    int m0 = (warp & 3) << 4;
    int n0 = (warp >> 2) << 5;
    int g = lane >> 2, tig = lane & 3;
    float acc[4][4];
#pragma unroll
    for (int s = 0; s < 4; s++) { acc[s][0] = acc[s][1] = acc[s][2] = acc[s][3] = 0.f; }
#pragma unroll
    for (int ks = 0; ks < 8; ks++) {
        int k0 = ks << 3;
        unsigned a0 = __float_as_uint(xs[(m0 + g)     * XA + k0 + tig]);
        unsigned a1 = __float_as_uint(xs[(m0 + g + 8) * XA + k0 + tig]);
        unsigned a2 = __float_as_uint(xs[(m0 + g)     * XA + k0 + tig + 4]);
        unsigned a3 = __float_as_uint(xs[(m0 + g + 8) * XA + k0 + tig + 4]);
#pragma unroll
        for (int sub = 0; sub < 4; sub++) {
            int n = n0 + (sub << 3) + g;
            unsigned b0 = __float_as_uint(Ws[(k0 + tig)     * WB + n]);
            unsigned b1 = __float_as_uint(Ws[(k0 + tig + 4) * WB + n]);
            mma_tf32(acc[sub], a0, a1, a2, a3, b0, b1);
        }
    }
    int rlo = m0 + g, rhi = m0 + g + 8;
    int row_lo = row0 + rlo, row_hi = row0 + rhi;
    float s0 = scal[rlo], s1 = scal[rhi];
#pragma unroll
    for (int sub = 0; sub < 4; sub++) {
        int col = n0 + (sub << 3) + (tig << 1);
        if (row_lo < N) {
            __half2 h = __floats2half2_rn(s0 * acc[sub][0], s0 * acc[sub][1]);
            *(__half2*)&hsh[(size_t)row_lo * DD + col] = h;
        }
        if (row_hi < N) {
            __half2 h = __floats2half2_rn(s1 * acc[sub][2], s1 * acc[sub][3]);
            *(__half2*)&hsh[(size_t)row_hi * DD + col] = h;
        }
    }
}

// Fused layer 2: concatenated-stream CSR aggregation (warp = 8 contiguous
// nodes = one contiguous epk range), relu(b1+dv*a), tf32 stage, mma W2.
__global__ void k_agg_gemm(const __half* __restrict__ hsh,
                           const int* __restrict__ rp, const unsigned* __restrict__ epk,
                           const float* __restrict__ W, const float* __restrict__ b,
                           const float* __restrict__ dv,
                           __half* __restrict__ out, int N) {
    __shared__ float Ws[DD * WB];
    __shared__ __align__(16) char uxs[DD * XA * 4];  // xs floats / sacc union
    __shared__ float dvs[64];
    __shared__ unsigned st[8][32];
    float* xs = (float*)uxs;
    float2 (*sacc)[8][32] = (float2 (*)[8][32])uxs;  // [warp][row][lane]
    int tid = threadIdx.x;
    int warp = tid >> 5, lane = tid & 31;
    int row0 = blockIdx.x * 64;

#pragma unroll
    for (int it = 0; it < 16; it++) {
        int i = it * 256 + tid;
        Ws[(i >> 6) * WB + (i & 63)] = __uint_as_float(f2tf32(W[i]));
    }
    if (tid < 64) {
        int row = row0 + tid;
        dvs[tid] = (row < N) ? dv[row] : 0.f;
    }
    // zero this warp's sacc rows
#pragma unroll
    for (int q = 0; q < 8; q++) sacc[warp][q][lane] = make_float2(0.f, 0.f);
    __syncthreads();

    // ---- concatenated aggregation ----
    int n0 = row0 + (warp << 3);
    int bidx = n0 + lane; if (bidx > N) bidx = N;
    int myb = rp[bidx];                       // lane i<=8 holds rp[n0+i]
    int bb0 = __shfl_sync(0xffffffffu, myb, 0);
    int bb8 = __shfl_sync(0xffffffffu, myb, 8);
    int c2 = lane << 1;
    int cur = 0;
    int nxt = __shfl_sync(0xffffffffu, myb, 1);
    float2 run = make_float2(0.f, 0.f);
    for (int j0 = bb0; j0 < bb8; j0 += 32) {
        int j = j0 + lane;
        st[warp][lane] = __ldg(&epk[(j < bb8) ? j : (bb8 - 1)]);
        __syncwarp();
#pragma unroll
        for (int k = 0; k < 32; k++) {
            int jk = j0 + k;
            if (jk < bb8) {
                while (jk >= nxt) {           // row boundary: flush once per row
                    sacc[warp][cur][lane] = run;
                    run.x = 0.f; run.y = 0.f;
                    cur++;
                    nxt = __shfl_sync(0xffffffffu, myb, cur + 1);
                }
                int s; float w; dec_epk(st[warp][k], s, w);
                float2 hv = __half22float2(*(const __half2*)&hsh[(size_t)s * DD + c2]);
                run.x += w * hv.x;
                run.y += w * hv.y;
            }
        }
        __syncwarp();
    }
    sacc[warp][cur][lane] = run;              // final flush
    __syncwarp();

    // ---- epilogue: read sacc to regs, then overwrite union with xs ----
    float2 areg[8];
#pragma unroll
    for (int q = 0; q < 8; q++) areg[q] = sacc[warp][q][lane];
    __syncthreads();                           // all reads before any xs write
    float bx = __ldg(&b[c2]), by = __ldg(&b[c2 + 1]);
#pragma unroll
    for (int q = 0; q < 8; q++) {
        int r = (warp << 3) + q;
        int n = row0 + r;
        float vx = 0.f, vy = 0.f;
        if (n < N) {
            float2 self = __half22float2(*(const __half2*)&hsh[(size_t)n * DD + c2]);
            float ax = areg[q].x + self.x;
            float ay = areg[q].y + self.y;
            float dn = dvs[r];
            vx = fmaxf(bx + dn * ax, 0.f);
            vy = fmaxf(by + dn * ay, 0.f);
        }
        xs[r * XA + c2]     = __uint_as_float(f2tf32(vx));
        xs[r * XA + c2 + 1] = __uint_as_float(f2tf32(vy));
    }
    __syncthreads();

    // ---- mma phase ----
    int m0 = (warp & 3) << 4;
    int nb0 = (warp >> 2) << 5;
    int g = lane >> 2, tig = lane & 3;
    float acc[4][4];
#pragma unroll
    for (int s = 0; s < 4; s++) { acc[s][0] = acc[s][1] = acc[s][2] = acc[s][3] = 0.f; }
#pragma unroll
    for (int ks = 0; ks < 8; ks++) {
        int k0 = ks << 3;
        unsigned a0 = __float_as_uint(xs[(m0 + g)     * XA + k0 + tig]);
        unsigned a1 = __float_as_uint(xs[(m0 + g + 8) * XA + k0 + tig]);
        unsigned a2 = __float_as_uint(xs[(m0 + g)     * XA + k0 + tig + 4]);
        unsigned a3 = __float_as_uint(xs[(m0 + g + 8) * XA + k0 + tig + 4]);
#pragma unroll
        for (int sub = 0; sub < 4; sub++) {
            int n = nb0 + (sub << 3) + g;
            unsigned b0 = __float_as_uint(Ws[(k0 + tig)     * WB + n]);
            unsigned b1 = __float_as_uint(Ws[(k0 + tig + 4) * WB + n]);
            mma_tf32(acc[sub], a0, a1, a2, a3, b0, b1);
        }
    }
    int rlo = m0 + g, rhi = m0 + g + 8;
    int row_lo = row0 + rlo, row_hi = row0 + rhi;
    float s0 = dvs[rlo], s1 = dvs[rhi];
#pragma unroll
    for (int sub = 0; sub < 4; sub++) {
        int col = nb0 + (sub << 3) + (tig << 1);
        if (row_lo < N) {
            __half2 h = __floats2half2_rn(s0 * acc[sub][0], s0 * acc[sub][1]);
            *(__half2*)&out[(size_t)row_lo * DD + col] = h;
        }
        if (row_hi < N) {
            __half2 h = __floats2half2_rn(s1 * acc[sub][2], s1 * acc[sub][3]);
            *(__half2*)&out[(size_t)row_hi * DD + col] = h;
        }
    }
}

// Fused layer 3 head: concatenated-stream aggregation over hsh2, then
// h3s[n] = dv[n] * ( relu(b2 + dv[n]*a) . W3 ).  Warp = 8 nodes.
__global__ void k_agg_dot(const __half* __restrict__ hsh2,
                          const int* __restrict__ rp, const unsigned* __restrict__ epk,
                          const float* __restrict__ W3, const float* __restrict__ b2,
                          const float* __restrict__ dv,
                          float* __restrict__ h3s, int N) {
    __shared__ float2 sacc[8][8][32];
    __shared__ unsigned st[8][32];
    int tid = threadIdx.x;
    int warp = tid >> 5, lane = tid & 31;
    int n0 = blockIdx.x * 64 + (warp << 3);
    int c2 = lane << 1;

#pragma unroll
    for (int q = 0; q < 8; q++) sacc[warp][q][lane] = make_float2(0.f, 0.f);

    int bidx = n0 + lane; if (bidx > N) bidx = N;
    int myb = rp[bidx];
    int bb0 = __shfl_sync(0xffffffffu, myb, 0);
    int bb8 = __shfl_sync(0xffffffffu, myb, 8);
    int cur = 0;
    int nxt = __shfl_sync(0xffffffffu, myb, 1);
    float2 run = make_float2(0.f, 0.f);
    for (int j0 = bb0; j0 < bb8; j0 += 32) {
        int j = j0 + lane;
        st[warp][lane] = __ldg(&epk[(j < bb8) ? j : (bb8 - 1)]);
        __syncwarp();
#pragma unroll
        for (int k = 0; k < 32; k++) {
            int jk = j0 + k;
            if (jk < bb8) {
                while (jk >= nxt) {
                    sacc[warp][cur][lane] = run;
                    run.x = 0.f; run.y = 0.f;
                    cur++;
                    nxt = __shfl_sync(0xffffffffu, myb, cur + 1);
                }
                int s; float w; dec_epk(st[warp][k], s, w);
                float2 hv = __half22float2(*(const __half2*)&hsh2[(size_t)s * DD + c2]);
                run.x += w * hv.x;
                run.y += w * hv.y;
            }
        }
        __syncwarp();
    }
    sacc[warp][cur][lane] = run;
    __syncwarp();

    float w3x = __ldg(&W3[c2]), w3y = __ldg(&W3[c2 + 1]);
    float bx = __ldg(&b2[c2]),  by = __ldg(&b2[c2 + 1]);
#pragma unroll
    for (int q = 0; q < 8; q++) {
        int n = n0 + q;
        if (n >= N) break;
        float d = __ldg(&dv[n]);
        float2 a = sacc[warp][q][lane];
        float2 self = __half22float2(*(const __half2*)&hsh2[(size_t)n * DD + c2]);
        float v0 = fmaxf(bx + d * (a.x + self.x), 0.f);
        float v1 = fmaxf(by + d * (a.y + self.y), 0.f);
        float s = v0 * w3x + v1 * w3y;
#pragma unroll
        for (int o = 16; o > 0; o >>= 1) s += __shfl_xor_sync(0xffffffffu, s, o);
        if (lane == 0) h3s[n] = d * s;
    }
}

// out[n] = b3 + dv[n] * ( h3s[n] + sum w*h3s[src] )   (warp per node)
__global__ void k_agg3(const float* __restrict__ h3s, float* __restrict__ out,
                       const int* __restrict__ rp, const unsigned* __restrict__ epk,
                       const float* __restrict__ b3, const float* __restrict__ dv,
                       int N) {
    int n = (blockIdx.x * blockDim.x + threadIdx.x) >> 5;
    int lane = threadIdx.x & 31;
    if (n >= N) return;
    int beg = rp[n], end = rp[n + 1];
    float t = 0.f;
    for (int j = beg + lane; j < end; j += 32) {
        int s; float w; dec_epk(__ldg(&epk[j]), s, w);
        t += w * __ldg(&h3s[s]);
    }
#pragma unroll
    for (int o = 16; o > 0; o >>= 1) t += __shfl_xor_sync(0xffffffffu, t, o);
    if (lane == 0) out[n] = __ldg(&b3[0]) + __ldg(&dv[n]) * (h3s[n] + t);
}

// ---------------- launch ----------------

extern "C" void kernel_launch(void* const* d_in, const int* in_sizes, int n_in,
                              void* d_out, int out_size) {
    const float* feat = (const float*)d_in[0];
    const int*   ei   = (const int*)d_in[1];   // int32 (JAX x64 disabled)
    const float* ev   = (const float*)d_in[2];
    const float* W1   = (const float*)d_in[3];
    const float* b1   = (const float*)d_in[4];
    const float* W2   = (const float*)d_in[5];
    const float* b2   = (const float*)d_in[6];
    const float* W3   = (const float*)d_in[7];
    const float* b3   = (const float*)d_in[8];
    float* out = (float*)d_out;

    int N = in_sizes[0] / DD;
    int E = in_sizes[2];
    const int* src = ei;
    const int* dst = ei + E;

    float *zbuf, *dvp, *ph3s;
    __half *phsh, *phsh2;
    unsigned* epk;
    int *rp, *cur, *bsum;
    cudaGetSymbolAddress((void**)&zbuf,  g_zbuf);
    cudaGetSymbolAddress((void**)&rp,    g_rp);
    cudaGetSymbolAddress((void**)&cur,   g_cur);
    cudaGetSymbolAddress((void**)&bsum,  g_bsum);
    cudaGetSymbolAddress((void**)&dvp,   g_dv);
    cudaGetSymbolAddress((void**)&epk,   g_epk);
    cudaGetSymbolAddress((void**)&phsh,  g_hsh);
    cudaGetSymbolAddress((void**)&phsh2, g_hsh2);
    cudaGetSymbolAddress((void**)&ph3s,  g_h3s);

    float* dr  = zbuf;                 // deg_row
    int*   cnt = (int*)(zbuf + NN);    // dst histogram

    int nb  = (N + 255) / 256;
    int ebl = (E + 255) / 256;
    int wnb = (N * 32 + 255) / 256;
    int gemm_blocks = (N + 63) / 64;

    cudaMemsetAsync(zbuf, 0, 2 * NN * sizeof(float), 0);

    k_pre1   <<<ebl, 256>>>(src, dst, ev, dr, cnt, E);
    k_scan1  <<<SCAN_NB, SCAN_BS>>>(cnt, rp, bsum, N);
    k_scan3  <<<nb, 256>>>(rp, cur, bsum, N, E);
    k_scatter<<<ebl, 256>>>(src, dst, ev, dr, cur, epk, E);

    // layer 1: feat -> hsh ; also emits dv[] (deg from epk, rowsum in-kernel)
    k_gemm0   <<<gemm_blocks, 256>>>(feat, W1, rp, epk, dvp, phsh, N);
    // layer 2: fused concatenated agg + relu + GEMM(W2) -> hsh2
    k_agg_gemm<<<gemm_blocks, 256>>>(phsh, rp, epk, W2, b1, dvp, phsh2, N);
    // layer 3 head: fused concatenated agg + relu + dot(W3) -> h3s
    k_agg_dot <<<gemm_blocks, 256>>>(phsh2, rp, epk, W3, b2, dvp, ph3s, N);
    // final aggregation
    k_agg3    <<<wnb, 256>>>(ph3s, out, rp, epk, b3, dvp, N);
}

// round 10
// speedup vs baseline: 1.2713x; 1.2713x over previous
#include <cuda_runtime.h>
#include <cuda_fp16.h>

#define NN 100000
#define EE 1600000
#define DD 64
#define SCAN_BS 1024
#define SCAN_NB ((NN + SCAN_BS - 1) / SCAN_BS)   // 98

// ---- scratch (static device globals; no allocation anywhere) ----
__device__ float    g_zbuf[2 * NN];            // [dr | cnt], one memset
__device__ int      g_rp[NN + 1];              // CSR row_ptr (by dst)
__device__ int      g_cur[NN];                 // scatter cursors
__device__ int      g_bsum[SCAN_NB];           // scan block sums
__device__ float    g_dv[NN];                  // dinv (written by k_gemm0)
__device__ unsigned g_epk[EE];                 // CSR: (src<<15) | fp16(w) sans sign
__device__ __align__(16) __half g_hsh[NN * DD];   // fp16: dinv * (x@W1)
__device__ __align__(16) __half g_hsh2[NN * DD];  // fp16: dinv * (x2@W2)
__device__ float g_h3s[NN];

__device__ __forceinline__ float guard1(float v) { return v > 0.f ? v : 1.f; }

__device__ __forceinline__ unsigned f2tf32(float v) {
    unsigned t;
    asm("cvt.rna.tf32.f32 %0, %1;" : "=r"(t) : "f"(v));
    return t;
}

__device__ __forceinline__ void mma_tf32(float* d,
                                         unsigned a0, unsigned a1, unsigned a2, unsigned a3,
                                         unsigned b0, unsigned b1) {
    asm volatile(
        "mma.sync.aligned.m16n8k8.row.col.f32.tf32.tf32.f32 "
        "{%0,%1,%2,%3}, {%4,%5,%6,%7}, {%8,%9}, {%0,%1,%2,%3};"
        : "+f"(d[0]), "+f"(d[1]), "+f"(d[2]), "+f"(d[3])
        : "r"(a0), "r"(a1), "r"(a2), "r"(a3), "r"(b0), "r"(b1));
}

__device__ __forceinline__ void dec_epk(unsigned v, int& s, float& w) {
    s = (int)(v >> 15);
    w = __half2float(__ushort_as_half((unsigned short)(v & 0x7FFFu)));
}
__device__ __forceinline__ float dec_w(unsigned v) {
    return __half2float(__ushort_as_half((unsigned short)(v & 0x7FFFu)));
}

// ---------------- precompute ----------------

__global__ void k_pre1(const int* __restrict__ src, const int* __restrict__ dst,
                       const float* __restrict__ ev,
                       float* __restrict__ dr, int* __restrict__ cnt, int E) {
    int e = blockIdx.x * blockDim.x + threadIdx.x;
    if (e >= E) return;
    atomicAdd(&dr[src[e]], ev[e]);
    atomicAdd(&cnt[dst[e]], 1);
}

__global__ void k_scan1(const int* __restrict__ cnt, int* __restrict__ rp,
                        int* __restrict__ bsum, int N) {
    __shared__ int ws[32];
    int t = threadIdx.x;
    int lane = t & 31, wid = t >> 5;
    int i = blockIdx.x * SCAN_BS + t;
    int v = (i < N) ? cnt[i] : 0;
    int x = v;
#pragma unroll
    for (int o = 1; o < 32; o <<= 1) {
        int y = __shfl_up_sync(0xffffffffu, x, o);
        if (lane >= o) x += y;
    }
    if (lane == 31) ws[wid] = x;
    __syncthreads();
    if (wid == 0) {
        int s = ws[lane];
#pragma unroll
        for (int o = 1; o < 32; o <<= 1) {
            int y = __shfl_up_sync(0xffffffffu, s, o);
            if (lane >= o) s += y;
        }
        ws[lane] = s;
    }
    __syncthreads();
    int incl = x + (wid ? ws[wid - 1] : 0);
    if (i < N) rp[i] = incl - v;
    if (t == SCAN_BS - 1) bsum[blockIdx.x] = incl;
}

__global__ void k_scan3(int* __restrict__ rp, int* __restrict__ cur,
                        const int* __restrict__ bsum, int N, int E) {
    __shared__ int sh[128];
    int t = threadIdx.x;
    if (t < 128) sh[t] = (t < SCAN_NB) ? bsum[t] : 0;
    __syncthreads();
#pragma unroll
    for (int o = 1; o < 128; o <<= 1) {
        int add = (t >= o && t < 128) ? sh[t - o] : 0;
        __syncthreads();
        if (t < 128) sh[t] += add;
        __syncthreads();
    }
    int i = blockIdx.x * blockDim.x + t;
    if (i >= N) return;
    int blk = i >> 10;
    int off = blk ? sh[blk - 1] : 0;
    int r = rp[i] + off;
    rp[i] = r;
    cur[i] = r;
    if (i == 0) rp[N] = E;
}

// w_hat compute + packed CSR scatter (no deg atomics)
__global__ void k_scatter(const int* __restrict__ src, const int* __restrict__ dst,
                          const float* __restrict__ ev, const float* __restrict__ dr,
                          int* __restrict__ cur, unsigned* __restrict__ epk, int E) {
    int e = blockIdx.x * blockDim.x + threadIdx.x;
    if (e >= E) return;
    int s = src[e], d = dst[e];
    float w = ev[e] / (guard1(__ldg(&dr[s])) * guard1(__ldg(&dr[d])));
    int p = atomicAdd(&cur[d], 1);
    unsigned hb = (unsigned)__half_as_ushort(__float2half_rn(w));  // w>0: bit15=0
    epk[p] = ((unsigned)s << 15) | hb;
}

// ---------------- layers ----------------

#define XA 68   // xs stride: conflict-free A-frag loads
#define WB 72   // Ws stride: conflict-free B-frag loads

// Layer 1 GEMM. Also computes deg (sum of epk w per row) -> dv[] for all
// later kernels, and rowsum(feat). hsh = half(dv/rowsum * feat@W1).
__global__ void k_gemm0(const float* __restrict__ in, const float* __restrict__ W,
                        const int* __restrict__ rp, const unsigned* __restrict__ epk,
                        float* __restrict__ dvout, __half* __restrict__ hsh, int N) {
    __shared__ float Ws[DD * WB];
    __shared__ float xs[DD * XA];
    __shared__ float sdg[64];
    __shared__ float scal[64];
    int tid = threadIdx.x;
    int warp = tid >> 5, lane = tid & 31;
    int row0 = blockIdx.x * 64;

#pragma unroll
    for (int it = 0; it < 16; it++) {
        int i = it * 256 + tid;
        Ws[(i >> 6) * WB + (i & 63)] = __uint_as_float(f2tf32(W[i]));
    }
#pragma unroll
    for (int it = 0; it < 16; it++) {
        int i = it * 256 + tid;
        int r = i >> 6, c = i & 63;
        int row = row0 + r;
        xs[r * XA + c] = (row < N) ? in[(size_t)row * DD + c] : 0.f;
    }
    // deg sums: warp per 8 rows (coalesced epk sweep)
#pragma unroll
    for (int q = 0; q < 8; q++) {
        int r = (warp << 3) + q;
        int n = row0 + r;
        float s = 0.f;
        if (n < N) {
            int beg = rp[n], end = rp[n + 1];
            for (int j = beg + lane; j < end; j += 32) s += dec_w(__ldg(&epk[j]));
        }
#pragma unroll
        for (int o = 16; o > 0; o >>= 1) s += __shfl_xor_sync(0xffffffffu, s, o);
        if (lane == 0) sdg[r] = s;
    }
    __syncthreads();
    if (tid < 64) {
        int row = row0 + tid;
        float s = 0.f;
        const float* xr = &xs[tid * XA];
#pragma unroll
        for (int c = 0; c < DD; c++) s += xr[c];
        float dv = rsqrtf(1.f + sdg[tid]);
        scal[tid] = dv / fmaxf(s, 1e-30f);
        if (row < N) dvout[row] = dv;
    }
    __syncthreads();
#pragma unroll
    for (int it = 0; it < 16; it++) {
        int i = it * 256 + tid;
        int r = i >> 6, c = i & 63;
        xs[r * XA + c] = __uint_as_float(f2tf32(xs[r * XA + c]));
    }
    __syncthreads();

    int m0 = (warp & 3) << 4;
    int n0 = (warp >> 2) << 5;
    int g = lane >> 2, tig = lane & 3;
    float acc[4][4];
#pragma unroll
    for (int s = 0; s < 4; s++) { acc[s][0] = acc[s][1] = acc[s][2] = acc[s][3] = 0.f; }
#pragma unroll
    for (int ks = 0; ks < 8; ks++) {
        int k0 = ks << 3;
        unsigned a0 = __float_as_uint(xs[(m0 + g)     * XA + k0 + tig]);
        unsigned a1 = __float_as_uint(xs[(m0 + g + 8) * XA + k0 + tig]);
        unsigned a2 = __float_as_uint(xs[(m0 + g)     * XA + k0 + tig + 4]);
        unsigned a3 = __float_as_uint(xs[(m0 + g + 8) * XA + k0 + tig + 4]);
#pragma unroll
        for (int sub = 0; sub < 4; sub++) {
            int n = n0 + (sub << 3) + g;
            unsigned b0 = __float_as_uint(Ws[(k0 + tig)     * WB + n]);
            unsigned b1 = __float_as_uint(Ws[(k0 + tig + 4) * WB + n]);
            mma_tf32(acc[sub], a0, a1, a2, a3, b0, b1);
        }
    }
    int rlo = m0 + g, rhi = m0 + g + 8;
    int row_lo = row0 + rlo, row_hi = row0 + rhi;
    float s0 = scal[rlo], s1 = scal[rhi];
#pragma unroll
    for (int sub = 0; sub < 4; sub++) {
        int col = n0 + (sub << 3) + (tig << 1);
        if (row_lo < N) {
            __half2 h = __floats2half2_rn(s0 * acc[sub][0], s0 * acc[sub][1]);
            *(__half2*)&hsh[(size_t)row_lo * DD + col] = h;
        }
        if (row_hi < N) {
            __half2 h = __floats2half2_rn(s1 * acc[sub][2], s1 * acc[sub][3]);
            *(__half2*)&hsh[(size_t)row_hi * DD + col] = h;
        }
    }
}

// Fused layer 2 (R8-style per-row staged agg): aggregate from hsh, apply
// relu(b1+dv*a), stage tf32, mma with W2; out = half(dv * (x2@W2)).
__global__ void k_agg_gemm(const __half* __restrict__ hsh,
                           const int* __restrict__ rp, const unsigned* __restrict__ epk,
                           const float* __restrict__ W, const float* __restrict__ b,
                           const float* __restrict__ dv,
                           __half* __restrict__ out, int N) {
    __shared__ float Ws[DD * WB];
    __shared__ float xs[DD * XA];
    __shared__ float dvs[64];
    __shared__ unsigned st[8][32];
    int tid = threadIdx.x;
    int warp = tid >> 5, lane = tid & 31;
    int row0 = blockIdx.x * 64;

#pragma unroll
    for (int it = 0; it < 16; it++) {
        int i = it * 256 + tid;
        Ws[(i >> 6) * WB + (i & 63)] = __uint_as_float(f2tf32(W[i]));
    }
    if (tid < 64) {
        int row = row0 + tid;
        dvs[tid] = (row < N) ? dv[row] : 0.f;
    }
    __syncthreads();

    int c2 = lane << 1;
    float bx = __ldg(&b[c2]), by = __ldg(&b[c2 + 1]);
#pragma unroll
    for (int q = 0; q < 8; q++) {
        int r = (warp << 3) + q;
        int n = row0 + r;
        float vx = 0.f, vy = 0.f;
        if (n < N) {
            float2 a = __half22float2(*(const __half2*)&hsh[(size_t)n * DD + c2]);
            int beg = rp[n], end = rp[n + 1];
            for (int j0 = beg; j0 < end; j0 += 32) {
                int m = end - j0;
                int jl = j0 + ((lane < m) ? lane : (m - 1));
                st[warp][lane] = __ldg(&epk[jl]);
                __syncwarp();
                if (m >= 32) {
#pragma unroll 8
                    for (int k = 0; k < 32; k++) {
                        int s; float w; dec_epk(st[warp][k], s, w);
                        float2 hv = __half22float2(*(const __half2*)&hsh[(size_t)s * DD + c2]);
                        a.x += w * hv.x;
                        a.y += w * hv.y;
                    }
                } else {
                    for (int k = 0; k < m; k++) {
                        int s; float w; dec_epk(st[warp][k], s, w);
                        float2 hv = __half22float2(*(const __half2*)&hsh[(size_t)s * DD + c2]);
                        a.x += w * hv.x;
                        a.y += w * hv.y;
                    }
                }
                __syncwarp();
            }
            float dn = dvs[r];
            vx = fmaxf(bx + dn * a.x, 0.f);
            vy = fmaxf(by + dn * a.y, 0.f);
        }
        xs[r * XA + c2]     = __uint_as_float(f2tf32(vx));
        xs[r * XA + c2 + 1] = __uint_as_float(f2tf32(vy));
    }
    __syncthreads();

    int m0 = (warp & 3) << 4;
    int nb0 = (warp >> 2) << 5;
    int g = lane >> 2, tig = lane & 3;
    float acc[4][4];
#pragma unroll
    for (int s = 0; s < 4; s++) { acc[s][0] = acc[s][1] = acc[s][2] = acc[s][3] = 0.f; }
#pragma unroll
    for (int ks = 0; ks < 8; ks++) {
        int k0 = ks << 3;
        unsigned a0 = __float_as_uint(xs[(m0 + g)     * XA + k0 + tig]);
        unsigned a1 = __float_as_uint(xs[(m0 + g + 8) * XA + k0 + tig]);
        unsigned a2 = __float_as_uint(xs[(m0 + g)     * XA + k0 + tig + 4]);
        unsigned a3 = __float_as_uint(xs[(m0 + g + 8) * XA + k0 + tig + 4]);
#pragma unroll
        for (int sub = 0; sub < 4; sub++) {
            int n = nb0 + (sub << 3) + g;
            unsigned b0 = __float_as_uint(Ws[(k0 + tig)     * WB + n]);
            unsigned b1 = __float_as_uint(Ws[(k0 + tig + 4) * WB + n]);
            mma_tf32(acc[sub], a0, a1, a2, a3, b0, b1);
        }
    }
    int rlo = m0 + g, rhi = m0 + g + 8;
    int row_lo = row0 + rlo, row_hi = row0 + rhi;
    float s0 = dvs[rlo], s1 = dvs[rhi];
#pragma unroll
    for (int sub = 0; sub < 4; sub++) {
        int col = nb0 + (sub << 3) + (tig << 1);
        if (row_lo < N) {
            __half2 h = __floats2half2_rn(s0 * acc[sub][0], s0 * acc[sub][1]);
            *(__half2*)&out[(size_t)row_lo * DD + col] = h;
        }
        if (row_hi < N) {
            __half2 h = __floats2half2_rn(s1 * acc[sub][2], s1 * acc[sub][3]);
            *(__half2*)&out[(size_t)row_hi * DD + col] = h;
        }
    }
}

// Fused layer 3 head (R8-style warp-per-node): aggregate from hsh2, then
// h3s[n] = dv[n] * ( relu(b2 + dv[n]*a) . W3 )
__global__ void k_agg_dot(const __half* __restrict__ hsh2,
                          const int* __restrict__ rp, const unsigned* __restrict__ epk,
                          const float* __restrict__ W3, const float* __restrict__ b2,
                          const float* __restrict__ dv,
                          float* __restrict__ h3s, int N) {
    __shared__ unsigned st[8][32];
    int wid  = threadIdx.x >> 5;
    int lane = threadIdx.x & 31;
    int n = (blockIdx.x * blockDim.x + threadIdx.x) >> 5;
    if (n >= N) return;
    int c2 = lane << 1;
    float2 a = __half22float2(*(const __half2*)&hsh2[(size_t)n * DD + c2]);
    int beg = rp[n], end = rp[n + 1];
    for (int j0 = beg; j0 < end; j0 += 32) {
        int m = end - j0;
        int jl = j0 + ((lane < m) ? lane : (m - 1));
        st[wid][lane] = __ldg(&epk[jl]);
        __syncwarp();
        if (m >= 32) {
#pragma unroll 8
            for (int k = 0; k < 32; k++) {
                int s; float w; dec_epk(st[wid][k], s, w);
                float2 hv = __half22float2(*(const __half2*)&hsh2[(size_t)s * DD + c2]);
                a.x += w * hv.x;
                a.y += w * hv.y;
            }
        } else {
            for (int k = 0; k < m; k++) {
                int s; float w; dec_epk(st[wid][k], s, w);
                float2 hv = __half22float2(*(const __half2*)&hsh2[(size_t)s * DD + c2]);
                a.x += w * hv.x;
                a.y += w * hv.y;
            }
        }
        __syncwarp();
    }
    float d = __ldg(&dv[n]);
    float v0 = fmaxf(__ldg(&b2[c2])     + d * a.x, 0.f);
    float v1 = fmaxf(__ldg(&b2[c2 + 1]) + d * a.y, 0.f);
    float s = v0 * __ldg(&W3[c2]) + v1 * __ldg(&W3[c2 + 1]);
#pragma unroll
    for (int o = 16; o > 0; o >>= 1) s += __shfl_xor_sync(0xffffffffu, s, o);
    if (lane == 0) h3s[n] = d * s;
}

// out[n] = b3 + dv[n] * ( h3s[n] + sum w*h3s[src] )   (warp per node)
__global__ void k_agg3(const float* __restrict__ h3s, float* __restrict__ out,
                       const int* __restrict__ rp, const unsigned* __restrict__ epk,
                       const float* __restrict__ b3, const float* __restrict__ dv,
                       int N) {
    int n = (blockIdx.x * blockDim.x + threadIdx.x) >> 5;
    int lane = threadIdx.x & 31;
    if (n >= N) return;
    int beg = rp[n], end = rp[n + 1];
    float t = 0.f;
    for (int j = beg + lane; j < end; j += 32) {
        int s; float w; dec_epk(__ldg(&epk[j]), s, w);
        t += w * __ldg(&h3s[s]);
    }
#pragma unroll
    for (int o = 16; o > 0; o >>= 1) t += __shfl_xor_sync(0xffffffffu, t, o);
    if (lane == 0) out[n] = __ldg(&b3[0]) + __ldg(&dv[n]) * (h3s[n] + t);
}

// ---------------- launch ----------------

extern "C" void kernel_launch(void* const* d_in, const int* in_sizes, int n_in,
                              void* d_out, int out_size) {
    const float* feat = (const float*)d_in[0];
    const int*   ei   = (const int*)d_in[1];   // int32 (JAX x64 disabled)
    const float* ev   = (const float*)d_in[2];
    const float* W1   = (const float*)d_in[3];
    const float* b1   = (const float*)d_in[4];
    const float* W2   = (const float*)d_in[5];
    const float* b2   = (const float*)d_in[6];
    const float* W3   = (const float*)d_in[7];
    const float* b3   = (const float*)d_in[8];
    float* out = (float*)d_out;

    int N = in_sizes[0] / DD;
    int E = in_sizes[2];
    const int* src = ei;
    const int* dst = ei + E;

    float *zbuf, *dvp, *ph3s;
    __half *phsh, *phsh2;
    unsigned* epk;
    int *rp, *cur, *bsum;
    cudaGetSymbolAddress((void**)&zbuf,  g_zbuf);
    cudaGetSymbolAddress((void**)&rp,    g_rp);
    cudaGetSymbolAddress((void**)&cur,   g_cur);
    cudaGetSymbolAddress((void**)&bsum,  g_bsum);
    cudaGetSymbolAddress((void**)&dvp,   g_dv);
    cudaGetSymbolAddress((void**)&epk,   g_epk);
    cudaGetSymbolAddress((void**)&phsh,  g_hsh);
    cudaGetSymbolAddress((void**)&phsh2, g_hsh2);
    cudaGetSymbolAddress((void**)&ph3s,  g_h3s);

    float* dr  = zbuf;                 // deg_row
    int*   cnt = (int*)(zbuf + NN);    // dst histogram

    int nb  = (N + 255) / 256;
    int ebl = (E + 255) / 256;
    int wnb = (N * 32 + 255) / 256;
    int gemm_blocks = (N + 63) / 64;

    cudaMemsetAsync(zbuf, 0, 2 * NN * sizeof(float), 0);

    k_pre1   <<<ebl, 256>>>(src, dst, ev, dr, cnt, E);
    k_scan1  <<<SCAN_NB, SCAN_BS>>>(cnt, rp, bsum, N);
    k_scan3  <<<nb, 256>>>(rp, cur, bsum, N, E);
    k_scatter<<<ebl, 256>>>(src, dst, ev, dr, cur, epk, E);

    // layer 1: feat -> hsh ; also emits dv[] (deg from epk, rowsum in-kernel)
    k_gemm0   <<<gemm_blocks, 256>>>(feat, W1, rp, epk, dvp, phsh, N);
    // layer 2: fused agg(hsh) + relu(b1+dv*a) + GEMM(W2) -> hsh2
    k_agg_gemm<<<gemm_blocks, 256>>>(phsh, rp, epk, W2, b1, dvp, phsh2, N);
    // layer 3 head: fused agg(hsh2) + relu(b2+dv*a).W3 -> h3s
    k_agg_dot <<<wnb, 256>>>(phsh2, rp, epk, W3, b2, dvp, ph3s, N);
    // final aggregation
    k_agg3    <<<wnb, 256>>>(ph3s, out, rp, epk, b3, dvp, N);
}